// round 5
// baseline (speedup 1.0000x reference)
#include <cuda_runtime.h>

// LocalAttender — Round 5.
// A: 64-thread blocks (2-way channel split), whole grid resident in one wave
//    (kills the R4 wave-quantization tail on the att kernel).
// B: 16-channel blocks, grid 8192, <=64 regs -> 32 warps/SM.
// Shapes (fixed): guide [8,128,128,128] f32, value [8,128,64,64] f32,
//                 w_conv [9,128] f32, b_conv [9] f32, out [8,128,128,128] f32.

#define K9 9
#define CIN 128
#define HV 64
#define WV 64
#define HO 128
#define WO 128

typedef unsigned long long u64;

__device__ u64 g_att[8][64][2][2 * K9][32];   // 4.7 MB scratch

__device__ __forceinline__ u64 pk2(float lo, float hi) {
    u64 d; asm("mov.b64 %0, {%1,%2};" : "=l"(d) : "f"(lo), "f"(hi)); return d;
}
__device__ __forceinline__ void upk2(u64 v, float& lo, float& hi) {
    asm("mov.b64 {%0,%1}, %2;" : "=f"(lo), "=f"(hi) : "l"(v));
}
__device__ __forceinline__ u64 fma2(u64 a, u64 b, u64 c) {
    u64 d; asm("fma.rn.f32x2 %0, %1, %2, %3;" : "=l"(d) : "l"(a), "l"(b), "l"(c)); return d;
}
__device__ __forceinline__ u64 add2(u64 a, u64 b) {
    u64 d; asm("add.rn.f32x2 %0, %1, %2;" : "=l"(d) : "l"(a), "l"(b)); return d;
}

__device__ __forceinline__ void softmax9(float a[K9]) {
    float m = a[0];
#pragma unroll
    for (int k = 1; k < K9; ++k) m = fmaxf(m, a[k]);
    float s = 0.0f;
#pragma unroll
    for (int k = 0; k < K9; ++k) { a[k] = __expf(a[k] - m); s += a[k]; }
    float inv = 1.0f / s;
#pragma unroll
    for (int k = 0; k < K9; ++k) a[k] *= inv;
}

// ---------------------------------------------------------------------------
// Kernel A: att.  Grid = B*H*2 = 1024 blocks, 64 threads (2 warps).
// warp 0: channels 0..63 (incl. residual 0..8), warp 1: channels 64..127.
// 1024 blocks <= 10*148 capacity -> single fully-resident wave, no tail.
// ---------------------------------------------------------------------------
__global__ __launch_bounds__(64, 10)
void la_att_kernel(const float* __restrict__ guide,
                   const float* __restrict__ wconv,
                   const float* __restrict__ bconv) {
    __shared__ u64 w2_s[CIN * K9];             // 9216 B, packed (w,w), [c][k]
    __shared__ float b_s[K9];
    __shared__ u64 part[2][32][2 * K9 + 1];    // 9728 B

    const int tid  = threadIdx.x;
    const int warp = tid >> 5;
    const int lane = tid & 31;

    for (int i = tid; i < CIN * K9; i += 64) {
        int k = i >> 7, c = i & (CIN - 1);
        float v = wconv[i];
        w2_s[c * K9 + k] = pk2(v, v);
    }
    if (tid < K9) b_s[tid] = bconv[tid];
    __syncthreads();

    const int b     = blockIdx.x >> 7;
    const int h     = (blockIdx.x >> 1) & 63;
    const int set   = blockIdx.x & 1;
    const int wq    = (set << 5) + lane;       // value col
    const int cbase = warp << 6;               // 64 channels per warp

    u64 acc[K9][2];
#pragma unroll
    for (int k = 0; k < K9; ++k) { acc[k][0] = 0ull; acc[k][1] = 0ull; }

    const float* gp = guide + ((b * CIN + cbase) * HO + 2 * h) * WO + 2 * wq;
    const int GCS = HO * WO;                   // 16384

    if (warp == 0) {
#pragma unroll
        for (int c = 0; c < K9; ++c) {
            u64 G0 = *(const u64*)(gp + c * GCS);
            u64 G1 = *(const u64*)(gp + c * GCS + WO);
#pragma unroll
            for (int k = 0; k < K9; ++k) {
                u64 W = w2_s[c * K9 + k];
                acc[k][0] = fma2(G0, W, acc[k][0]);
                acc[k][1] = fma2(G1, W, acc[k][1]);
            }
            acc[c][0] = add2(acc[c][0], G0);   // residual guide[:, :9]
            acc[c][1] = add2(acc[c][1], G1);
        }
#pragma unroll 4
        for (int c = K9; c < 64; ++c) {
            u64 G0 = *(const u64*)(gp + c * GCS);
            u64 G1 = *(const u64*)(gp + c * GCS + WO);
#pragma unroll
            for (int k = 0; k < K9; ++k) {
                u64 W = w2_s[c * K9 + k];
                acc[k][0] = fma2(G0, W, acc[k][0]);
                acc[k][1] = fma2(G1, W, acc[k][1]);
            }
        }
    } else {
#pragma unroll 4
        for (int c = 0; c < 64; ++c) {
            u64 G0 = *(const u64*)(gp + c * GCS);
            u64 G1 = *(const u64*)(gp + c * GCS + WO);
#pragma unroll
            for (int k = 0; k < K9; ++k) {
                u64 W = w2_s[(cbase + c) * K9 + k];
                acc[k][0] = fma2(G0, W, acc[k][0]);
                acc[k][1] = fma2(G1, W, acc[k][1]);
            }
        }
    }

    // 2-way all-reduce through smem
#pragma unroll
    for (int k = 0; k < K9; ++k) {
        part[warp][lane][2 * k]     = acc[k][0];
        part[warp][lane][2 * k + 1] = acc[k][1];
    }
    __syncthreads();

    if (warp == 0) {
#pragma unroll
        for (int k = 0; k < K9; ++k) {
            acc[k][0] = add2(acc[k][0], part[1][lane][2 * k]);
            acc[k][1] = add2(acc[k][1], part[1][lane][2 * k + 1]);
        }
#pragma unroll
        for (int k = 0; k < K9; ++k) {
            u64 B = pk2(b_s[k], b_s[k]);
            acc[k][0] = add2(acc[k][0], B);
            acc[k][1] = add2(acc[k][1], B);
        }
#pragma unroll
        for (int r = 0; r < 2; ++r) {
            float a0[K9], a1[K9];
#pragma unroll
            for (int k = 0; k < K9; ++k) upk2(acc[k][r], a0[k], a1[k]);
            softmax9(a0);
            softmax9(a1);
#pragma unroll
            for (int k = 0; k < K9; ++k) acc[k][r] = pk2(a0[k], a1[k]);
        }
#pragma unroll
        for (int k = 0; k < K9; ++k) {
            g_att[b][h][set][2 * k][lane]     = acc[k][0];
            g_att[b][h][set][2 * k + 1][lane] = acc[k][1];
        }
    }
}

// ---------------------------------------------------------------------------
// Kernel B: output.  Grid = B*H*2*8 = 8192 blocks, 128 threads.
// Block = (b, h, set, channel-group of 16); warp w: channels [4w, 4w+4).
// value rows staged to SMEM (12 KB), att staged (4.6 KB); <=64 regs target
// -> 8 blocks/SM = 32 warps.
// ---------------------------------------------------------------------------
__global__ __launch_bounds__(128, 8)
void la_out_kernel(const float* __restrict__ value,
                   float* __restrict__ out) {
    __shared__ float vs[16][3][64];            // 12288 B
    __shared__ u64 att_s[2 * K9 * 32];         // 4608 B

    const int tid  = threadIdx.x;
    const int warp = tid >> 5;
    const int lane = tid & 31;

    const int cg  = blockIdx.x & 7;
    const int set = (blockIdx.x >> 3) & 1;
    const int h   = (blockIdx.x >> 4) & 63;
    const int b   = blockIdx.x >> 10;
    const int cblk = cg << 4;                  // block channel base (16 ch)

    const int ym1 = (h == 0) ? 0 : h - 1;
    const int yp1 = (h == HV - 1) ? HV - 1 : h + 1;

    // stage att (576 u64, coalesced)
    {
        const u64* reg = &g_att[b][h][set][0][0];
        for (int i = tid; i < 2 * K9 * 32; i += 128) att_s[i] = reg[i];
    }

    // stage value: 16 ch x 3 rows x 64 cols as float4 (768 vec4, 6/thread)
    {
        const float* vbase = value + (b * CIN + cblk) * (HV * WV);
        const int rowoff[3] = { ym1 * WV, h * WV, yp1 * WV };
#pragma unroll
        for (int it = 0; it < 6; ++it) {
            int i   = tid + it * 128;
            int c   = i / 48;
            int rem = i - c * 48;
            int r   = rem >> 4;
            int q   = rem & 15;
            float4 v4 = *(const float4*)(vbase + c * (HV * WV) + rowoff[r] + q * 4);
            *(float4*)&vs[c][r][q * 4] = v4;
        }
    }
    __syncthreads();

    const int wq  = (set << 5) + lane;         // global value col
    const int xm1 = (wq == 0) ? 0 : wq - 1;
    const int xp1 = (wq == WV - 1) ? WV - 1 : wq + 1;
    const int cth = warp << 2;                 // 4 channels per thread

    u64 acc[K9][2];
#pragma unroll
    for (int k = 0; k < K9; ++k) {
        acc[k][0] = att_s[(2 * k) * 32 + lane];
        acc[k][1] = att_s[(2 * k + 1) * 32 + lane];
    }

    float* op = out + ((b * CIN + cblk + cth) * HO + 2 * h) * WO + 2 * wq;
    const int GCS = HO * WO;                   // 16384

#pragma unroll
    for (int c = 0; c < 4; ++c) {
        const float* vr = &vs[cth + c][0][0];
        float nv[K9];
#pragma unroll
        for (int r = 0; r < 3; ++r) {
            nv[r * 3 + 0] = vr[r * 64 + xm1];
            nv[r * 3 + 1] = vr[r * 64 + wq];
            nv[r * 3 + 2] = vr[r * 64 + xp1];
        }
        u64 o0 = 0ull, o1 = 0ull;
#pragma unroll
        for (int k = 0; k < K9; ++k) {
            u64 NV = pk2(nv[k], nv[k]);
            o0 = fma2(acc[k][0], NV, o0);
            o1 = fma2(acc[k][1], NV, o1);
        }
        *(u64*)(op + c * GCS)      = o0;
        *(u64*)(op + c * GCS + WO) = o1;
    }
}

extern "C" void kernel_launch(void* const* d_in, const int* in_sizes, int n_in,
                              void* d_out, int out_size) {
    const float* guide = (const float*)d_in[0];
    const float* value = (const float*)d_in[1];
    const float* wconv = (const float*)d_in[2];
    const float* bconv = (const float*)d_in[3];
    float* out = (float*)d_out;
    (void)in_sizes; (void)n_in; (void)out_size;

    la_att_kernel<<<1024, 64>>>(guide, wconv, bconv);
    la_out_kernel<<<8192, 128>>>(value, out);
}

// round 6
// speedup vs baseline: 1.0158x; 1.0158x over previous
#include <cuda_runtime.h>

// LocalAttender — Round 5.
// A: 64-thread blocks (2-way channel split), whole grid resident in one wave
//    (kills the R4 wave-quantization tail on the att kernel).
// B: 16-channel blocks, grid 8192, <=64 regs -> 32 warps/SM.
// Shapes (fixed): guide [8,128,128,128] f32, value [8,128,64,64] f32,
//                 w_conv [9,128] f32, b_conv [9] f32, out [8,128,128,128] f32.

#define K9 9
#define CIN 128
#define HV 64
#define WV 64
#define HO 128
#define WO 128

typedef unsigned long long u64;

__device__ u64 g_att[8][64][2][2 * K9][32];   // 4.7 MB scratch

__device__ __forceinline__ u64 pk2(float lo, float hi) {
    u64 d; asm("mov.b64 %0, {%1,%2};" : "=l"(d) : "f"(lo), "f"(hi)); return d;
}
__device__ __forceinline__ void upk2(u64 v, float& lo, float& hi) {
    asm("mov.b64 {%0,%1}, %2;" : "=f"(lo), "=f"(hi) : "l"(v));
}
__device__ __forceinline__ u64 fma2(u64 a, u64 b, u64 c) {
    u64 d; asm("fma.rn.f32x2 %0, %1, %2, %3;" : "=l"(d) : "l"(a), "l"(b), "l"(c)); return d;
}
__device__ __forceinline__ u64 add2(u64 a, u64 b) {
    u64 d; asm("add.rn.f32x2 %0, %1, %2;" : "=l"(d) : "l"(a), "l"(b)); return d;
}

__device__ __forceinline__ void softmax9(float a[K9]) {
    float m = a[0];
#pragma unroll
    for (int k = 1; k < K9; ++k) m = fmaxf(m, a[k]);
    float s = 0.0f;
#pragma unroll
    for (int k = 0; k < K9; ++k) { a[k] = __expf(a[k] - m); s += a[k]; }
    float inv = 1.0f / s;
#pragma unroll
    for (int k = 0; k < K9; ++k) a[k] *= inv;
}

// ---------------------------------------------------------------------------
// Kernel A: att.  Grid = B*H*2 = 1024 blocks, 64 threads (2 warps).
// warp 0: channels 0..63 (incl. residual 0..8), warp 1: channels 64..127.
// 1024 blocks <= 10*148 capacity -> single fully-resident wave, no tail.
// ---------------------------------------------------------------------------
__global__ __launch_bounds__(64, 10)
void la_att_kernel(const float* __restrict__ guide,
                   const float* __restrict__ wconv,
                   const float* __restrict__ bconv) {
    __shared__ u64 w2_s[CIN * K9];             // 9216 B, packed (w,w), [c][k]
    __shared__ float b_s[K9];
    __shared__ u64 part[2][32][2 * K9 + 1];    // 9728 B

    const int tid  = threadIdx.x;
    const int warp = tid >> 5;
    const int lane = tid & 31;

    for (int i = tid; i < CIN * K9; i += 64) {
        int k = i >> 7, c = i & (CIN - 1);
        float v = wconv[i];
        w2_s[c * K9 + k] = pk2(v, v);
    }
    if (tid < K9) b_s[tid] = bconv[tid];
    __syncthreads();

    const int b     = blockIdx.x >> 7;
    const int h     = (blockIdx.x >> 1) & 63;
    const int set   = blockIdx.x & 1;
    const int wq    = (set << 5) + lane;       // value col
    const int cbase = warp << 6;               // 64 channels per warp

    u64 acc[K9][2];
#pragma unroll
    for (int k = 0; k < K9; ++k) { acc[k][0] = 0ull; acc[k][1] = 0ull; }

    const float* gp = guide + ((b * CIN + cbase) * HO + 2 * h) * WO + 2 * wq;
    const int GCS = HO * WO;                   // 16384

    if (warp == 0) {
#pragma unroll
        for (int c = 0; c < K9; ++c) {
            u64 G0 = *(const u64*)(gp + c * GCS);
            u64 G1 = *(const u64*)(gp + c * GCS + WO);
#pragma unroll
            for (int k = 0; k < K9; ++k) {
                u64 W = w2_s[c * K9 + k];
                acc[k][0] = fma2(G0, W, acc[k][0]);
                acc[k][1] = fma2(G1, W, acc[k][1]);
            }
            acc[c][0] = add2(acc[c][0], G0);   // residual guide[:, :9]
            acc[c][1] = add2(acc[c][1], G1);
        }
#pragma unroll 4
        for (int c = K9; c < 64; ++c) {
            u64 G0 = *(const u64*)(gp + c * GCS);
            u64 G1 = *(const u64*)(gp + c * GCS + WO);
#pragma unroll
            for (int k = 0; k < K9; ++k) {
                u64 W = w2_s[c * K9 + k];
                acc[k][0] = fma2(G0, W, acc[k][0]);
                acc[k][1] = fma2(G1, W, acc[k][1]);
            }
        }
    } else {
#pragma unroll 4
        for (int c = 0; c < 64; ++c) {
            u64 G0 = *(const u64*)(gp + c * GCS);
            u64 G1 = *(const u64*)(gp + c * GCS + WO);
#pragma unroll
            for (int k = 0; k < K9; ++k) {
                u64 W = w2_s[(cbase + c) * K9 + k];
                acc[k][0] = fma2(G0, W, acc[k][0]);
                acc[k][1] = fma2(G1, W, acc[k][1]);
            }
        }
    }

    // 2-way all-reduce through smem
#pragma unroll
    for (int k = 0; k < K9; ++k) {
        part[warp][lane][2 * k]     = acc[k][0];
        part[warp][lane][2 * k + 1] = acc[k][1];
    }
    __syncthreads();

    if (warp == 0) {
#pragma unroll
        for (int k = 0; k < K9; ++k) {
            acc[k][0] = add2(acc[k][0], part[1][lane][2 * k]);
            acc[k][1] = add2(acc[k][1], part[1][lane][2 * k + 1]);
        }
#pragma unroll
        for (int k = 0; k < K9; ++k) {
            u64 B = pk2(b_s[k], b_s[k]);
            acc[k][0] = add2(acc[k][0], B);
            acc[k][1] = add2(acc[k][1], B);
        }
#pragma unroll
        for (int r = 0; r < 2; ++r) {
            float a0[K9], a1[K9];
#pragma unroll
            for (int k = 0; k < K9; ++k) upk2(acc[k][r], a0[k], a1[k]);
            softmax9(a0);
            softmax9(a1);
#pragma unroll
            for (int k = 0; k < K9; ++k) acc[k][r] = pk2(a0[k], a1[k]);
        }
#pragma unroll
        for (int k = 0; k < K9; ++k) {
            g_att[b][h][set][2 * k][lane]     = acc[k][0];
            g_att[b][h][set][2 * k + 1][lane] = acc[k][1];
        }
    }
}

// ---------------------------------------------------------------------------
// Kernel B: output.  Grid = B*H*2*8 = 8192 blocks, 128 threads.
// Block = (b, h, set, channel-group of 16); warp w: channels [4w, 4w+4).
// value rows staged to SMEM (12 KB), att staged (4.6 KB); <=64 regs target
// -> 8 blocks/SM = 32 warps.
// ---------------------------------------------------------------------------
__global__ __launch_bounds__(128, 8)
void la_out_kernel(const float* __restrict__ value,
                   float* __restrict__ out) {
    __shared__ float vs[16][3][64];            // 12288 B
    __shared__ u64 att_s[2 * K9 * 32];         // 4608 B

    const int tid  = threadIdx.x;
    const int warp = tid >> 5;
    const int lane = tid & 31;

    const int cg  = blockIdx.x & 7;
    const int set = (blockIdx.x >> 3) & 1;
    const int h   = (blockIdx.x >> 4) & 63;
    const int b   = blockIdx.x >> 10;
    const int cblk = cg << 4;                  // block channel base (16 ch)

    const int ym1 = (h == 0) ? 0 : h - 1;
    const int yp1 = (h == HV - 1) ? HV - 1 : h + 1;

    // stage att (576 u64, coalesced)
    {
        const u64* reg = &g_att[b][h][set][0][0];
        for (int i = tid; i < 2 * K9 * 32; i += 128) att_s[i] = reg[i];
    }

    // stage value: 16 ch x 3 rows x 64 cols as float4 (768 vec4, 6/thread)
    {
        const float* vbase = value + (b * CIN + cblk) * (HV * WV);
        const int rowoff[3] = { ym1 * WV, h * WV, yp1 * WV };
#pragma unroll
        for (int it = 0; it < 6; ++it) {
            int i   = tid + it * 128;
            int c   = i / 48;
            int rem = i - c * 48;
            int r   = rem >> 4;
            int q   = rem & 15;
            float4 v4 = *(const float4*)(vbase + c * (HV * WV) + rowoff[r] + q * 4);
            *(float4*)&vs[c][r][q * 4] = v4;
        }
    }
    __syncthreads();

    const int wq  = (set << 5) + lane;         // global value col
    const int xm1 = (wq == 0) ? 0 : wq - 1;
    const int xp1 = (wq == WV - 1) ? WV - 1 : wq + 1;
    const int cth = warp << 2;                 // 4 channels per thread

    u64 acc[K9][2];
#pragma unroll
    for (int k = 0; k < K9; ++k) {
        acc[k][0] = att_s[(2 * k) * 32 + lane];
        acc[k][1] = att_s[(2 * k + 1) * 32 + lane];
    }

    float* op = out + ((b * CIN + cblk + cth) * HO + 2 * h) * WO + 2 * wq;
    const int GCS = HO * WO;                   // 16384

#pragma unroll
    for (int c = 0; c < 4; ++c) {
        const float* vr = &vs[cth + c][0][0];
        float nv[K9];
#pragma unroll
        for (int r = 0; r < 3; ++r) {
            nv[r * 3 + 0] = vr[r * 64 + xm1];
            nv[r * 3 + 1] = vr[r * 64 + wq];
            nv[r * 3 + 2] = vr[r * 64 + xp1];
        }
        u64 o0 = 0ull, o1 = 0ull;
#pragma unroll
        for (int k = 0; k < K9; ++k) {
            u64 NV = pk2(nv[k], nv[k]);
            o0 = fma2(acc[k][0], NV, o0);
            o1 = fma2(acc[k][1], NV, o1);
        }
        *(u64*)(op + c * GCS)      = o0;
        *(u64*)(op + c * GCS + WO) = o1;
    }
}

extern "C" void kernel_launch(void* const* d_in, const int* in_sizes, int n_in,
                              void* d_out, int out_size) {
    const float* guide = (const float*)d_in[0];
    const float* value = (const float*)d_in[1];
    const float* wconv = (const float*)d_in[2];
    const float* bconv = (const float*)d_in[3];
    float* out = (float*)d_out;
    (void)in_sizes; (void)n_in; (void)out_size;

    la_att_kernel<<<1024, 64>>>(guide, wconv, bconv);
    la_out_kernel<<<8192, 128>>>(value, out);
}